// round 3
// baseline (speedup 1.0000x reference)
#include <cuda_runtime.h>
#include <cstdint>

#define TOKENS 8192
#define DM     1024
#define LSEQ   2048
#define NB     4
#define NH     16
#define DK     64

// Scratch (device globals — no allocation in kernel_launch)
__device__ float g_h[TOKENS * DM];               // layernorm output
__device__ float g_qkv[(size_t)TOKENS * 3 * DM]; // qkv (rope applied in-place)
__device__ float g_o[TOKENS * DM];               // attention output

// ===========================================================================
// Helpers
// ===========================================================================
__device__ __forceinline__ float tf32_rna(float x) {
    uint32_t h;
    asm("cvt.rna.tf32.f32 %0, %1;" : "=r"(h) : "f"(x));
    return __uint_as_float(h);
}
__device__ __forceinline__ void mma_tf32(float* c, const uint32_t* a,
                                         const uint32_t* b) {
    asm volatile(
        "mma.sync.aligned.m16n8k8.row.col.f32.tf32.tf32.f32 "
        "{%0,%1,%2,%3}, {%4,%5,%6,%7}, {%8,%9}, {%0,%1,%2,%3};\n"
        : "+f"(c[0]), "+f"(c[1]), "+f"(c[2]), "+f"(c[3])
        : "r"(a[0]), "r"(a[1]), "r"(a[2]), "r"(a[3]), "r"(b[0]), "r"(b[1]));
}

// ===========================================================================
// LayerNorm: one block per row (1024 floats), 256 threads x float4
// ===========================================================================
__global__ __launch_bounds__(256) void ln_kernel(const float* __restrict__ x,
                                                 float* __restrict__ h) {
    int row = blockIdx.x;
    int t = threadIdx.x;
    const float4* xr = (const float4*)(x + (size_t)row * DM);
    float4 v = xr[t];
    float s  = v.x + v.y + v.z + v.w;
    float ss = v.x * v.x + v.y * v.y + v.z * v.z + v.w * v.w;
    #pragma unroll
    for (int off = 16; off; off >>= 1) {
        s  += __shfl_xor_sync(0xffffffffu, s, off);
        ss += __shfl_xor_sync(0xffffffffu, ss, off);
    }
    __shared__ float sh[16];
    __shared__ float sh_mu, sh_r;
    int warp = t >> 5, lane = t & 31;
    if (lane == 0) { sh[warp] = s; sh[warp + 8] = ss; }
    __syncthreads();
    if (t == 0) {
        float S = 0.f, SS = 0.f;
        #pragma unroll
        for (int w = 0; w < 8; w++) { S += sh[w]; SS += sh[w + 8]; }
        float mu  = S * (1.0f / DM);
        float var = SS * (1.0f / DM) - mu * mu;
        sh_mu = mu;
        sh_r  = rsqrtf(var + 1e-8f);
    }
    __syncthreads();
    float mu = sh_mu, r = sh_r;
    float4 o = make_float4((v.x - mu) * r, (v.y - mu) * r,
                           (v.z - mu) * r, (v.w - mu) * r);
    ((float4*)(h + (size_t)row * DM))[t] = o;
}

// ===========================================================================
// Split-tf32 mma.sync NT GEMM: C[M,N] = A[M,K] * B[N,K]^T, fp32 in/out.
// 128x128 CTA tile, BK=16, 8 warps (2x4), warp tile 64x32 of m16n8k8 frags.
// hi/lo decomposition (3 products) -> ~fp32 accuracy.
// ===========================================================================
#define BM 128
#define BN 128
#define BK 16
#define SROW 20                       // padded row stride (floats)
#define SARR (BM * SROW)              // 2560 floats per array
#define SSTAGE (4 * SARR)             // Ahi, Alo, Bhi, Blo
#define GEMM_SMEM (2 * SSTAGE * 4)    // bytes: 81920

__global__ __launch_bounds__(256) void gemm_tc(const float* __restrict__ A,
                                               const float* __restrict__ B,
                                               float* __restrict__ C,
                                               int M, int N_, int K) {
    extern __shared__ float sm[];
    int t = threadIdx.x;
    int lane = t & 31, wid = t >> 5;
    int wm = wid >> 2, wn = wid & 3;      // 2 x 4 warp grid
    int g = lane >> 2, t4 = lane & 3;
    int m0 = blockIdx.y * BM, n0 = blockIdx.x * BN;

    float acc[4][4][4];
    #pragma unroll
    for (int i = 0; i < 4; i++)
        #pragma unroll
        for (int j = 0; j < 4; j++)
            #pragma unroll
            for (int q = 0; q < 4; q++) acc[i][j][q] = 0.f;

    // global-load indexing: 512 float4 per matrix per stage; thread does 2
    int ar0 = t >> 2, aq0 = t & 3;              // f = t
    int ar1 = (t + 256) >> 2, aq1 = t & 3;      // f = t+256 (q same since +256 = +64 rows)

    const int NSTAGE = K / BK;
    float4 pa0, pa1, pb0, pb1;
    {
        const float* Ab = A + (size_t)m0 * K;
        const float* Bb = B + (size_t)n0 * K;
        pa0 = *(const float4*)(Ab + (size_t)ar0 * K + aq0 * 4);
        pa1 = *(const float4*)(Ab + (size_t)ar1 * K + aq1 * 4);
        pb0 = *(const float4*)(Bb + (size_t)ar0 * K + aq0 * 4);
        pb1 = *(const float4*)(Bb + (size_t)ar1 * K + aq1 * 4);
    }

    for (int sidx = 0; sidx < NSTAGE; sidx++) {
        float* Sb = sm + (sidx & 1) * SSTAGE;
        float* Ahi = Sb;
        float* Alo = Sb + SARR;
        float* Bhi = Sb + 2 * SARR;
        float* Blo = Sb + 3 * SARR;

        // store prefetched stage (hi/lo split)
        {
            float4 h0 = make_float4(tf32_rna(pa0.x), tf32_rna(pa0.y),
                                    tf32_rna(pa0.z), tf32_rna(pa0.w));
            float4 l0 = make_float4(tf32_rna(pa0.x - h0.x), tf32_rna(pa0.y - h0.y),
                                    tf32_rna(pa0.z - h0.z), tf32_rna(pa0.w - h0.w));
            *(float4*)(Ahi + ar0 * SROW + aq0 * 4) = h0;
            *(float4*)(Alo + ar0 * SROW + aq0 * 4) = l0;
            float4 h1 = make_float4(tf32_rna(pa1.x), tf32_rna(pa1.y),
                                    tf32_rna(pa1.z), tf32_rna(pa1.w));
            float4 l1 = make_float4(tf32_rna(pa1.x - h1.x), tf32_rna(pa1.y - h1.y),
                                    tf32_rna(pa1.z - h1.z), tf32_rna(pa1.w - h1.w));
            *(float4*)(Ahi + ar1 * SROW + aq1 * 4) = h1;
            *(float4*)(Alo + ar1 * SROW + aq1 * 4) = l1;
            float4 hb0 = make_float4(tf32_rna(pb0.x), tf32_rna(pb0.y),
                                     tf32_rna(pb0.z), tf32_rna(pb0.w));
            float4 lb0 = make_float4(tf32_rna(pb0.x - hb0.x), tf32_rna(pb0.y - hb0.y),
                                     tf32_rna(pb0.z - hb0.z), tf32_rna(pb0.w - hb0.w));
            *(float4*)(Bhi + ar0 * SROW + aq0 * 4) = hb0;
            *(float4*)(Blo + ar0 * SROW + aq0 * 4) = lb0;
            float4 hb1 = make_float4(tf32_rna(pb1.x), tf32_rna(pb1.y),
                                     tf32_rna(pb1.z), tf32_rna(pb1.w));
            float4 lb1 = make_float4(tf32_rna(pb1.x - hb1.x), tf32_rna(pb1.y - hb1.y),
                                     tf32_rna(pb1.z - hb1.z), tf32_rna(pb1.w - hb1.w));
            *(float4*)(Bhi + ar1 * SROW + aq1 * 4) = hb1;
            *(float4*)(Blo + ar1 * SROW + aq1 * 4) = lb1;
        }
        __syncthreads();

        // prefetch next stage
        if (sidx + 1 < NSTAGE) {
            int k0 = (sidx + 1) * BK;
            const float* Ab = A + (size_t)m0 * K + k0;
            const float* Bb = B + (size_t)n0 * K + k0;
            pa0 = *(const float4*)(Ab + (size_t)ar0 * K + aq0 * 4);
            pa1 = *(const float4*)(Ab + (size_t)ar1 * K + aq1 * 4);
            pb0 = *(const float4*)(Bb + (size_t)ar0 * K + aq0 * 4);
            pb1 = *(const float4*)(Bb + (size_t)ar1 * K + aq1 * 4);
        }

        // compute 2 k8 steps
        #pragma unroll
        for (int kk = 0; kk < 2; kk++) {
            int kb = kk * 8;
            uint32_t ah[4][4], al[4][4], bh[4][2], bl[4][2];
            #pragma unroll
            for (int mb = 0; mb < 4; mb++) {
                int r0 = (wm * 64 + mb * 16 + g) * SROW + kb + t4;
                int r8 = r0 + 8 * SROW;
                ah[mb][0] = __float_as_uint(Ahi[r0]);
                ah[mb][1] = __float_as_uint(Ahi[r8]);
                ah[mb][2] = __float_as_uint(Ahi[r0 + 4]);
                ah[mb][3] = __float_as_uint(Ahi[r8 + 4]);
                al[mb][0] = __float_as_uint(Alo[r0]);
                al[mb][1] = __float_as_uint(Alo[r8]);
                al[mb][2] = __float_as_uint(Alo[r0 + 4]);
                al[mb][3] = __float_as_uint(Alo[r8 + 4]);
            }
            #pragma unroll
            for (int nb = 0; nb < 4; nb++) {
                int c0 = (wn * 32 + nb * 8 + g) * SROW + kb + t4;
                bh[nb][0] = __float_as_uint(Bhi[c0]);
                bh[nb][1] = __float_as_uint(Bhi[c0 + 4]);
                bl[nb][0] = __float_as_uint(Blo[c0]);
                bl[nb][1] = __float_as_uint(Blo[c0 + 4]);
            }
            #pragma unroll
            for (int mb = 0; mb < 4; mb++)
                #pragma unroll
                for (int nb = 0; nb < 4; nb++) {
                    mma_tf32(acc[mb][nb], ah[mb], bh[nb]);
                    mma_tf32(acc[mb][nb], ah[mb], bl[nb]);
                    mma_tf32(acc[mb][nb], al[mb], bh[nb]);
                }
        }
        __syncthreads();
    }

    // epilogue
    #pragma unroll
    for (int mb = 0; mb < 4; mb++) {
        int row0 = m0 + wm * 64 + mb * 16 + g;
        #pragma unroll
        for (int nb = 0; nb < 4; nb++) {
            int col = n0 + wn * 32 + nb * 8 + 2 * t4;
            *(float2*)(C + (size_t)row0 * N_ + col) =
                make_float2(acc[mb][nb][0], acc[mb][nb][1]);
            *(float2*)(C + (size_t)(row0 + 8) * N_ + col) =
                make_float2(acc[mb][nb][2], acc[mb][nb][3]);
        }
    }
}

// ===========================================================================
// RoPE (interleaved) applied in-place to q and k slices of g_qkv.
// ===========================================================================
__global__ __launch_bounds__(512) void rope_kernel(float* __restrict__ qkv) {
    int token = blockIdx.x;
    int p = threadIdx.x;
    int head = p >> 5;
    int i = p & 31;
    int l = token & (LSEQ - 1);
    double inv = pow(10000.0, -(double)i / 32.0);
    double ang = (double)l * inv;
    double snd, csd;
    sincos(ang, &snd, &csd);
    float sn = (float)snd, cs = (float)csd;
    size_t base = (size_t)token * 3 * DM + head * DK + 2 * i;
    float x1 = qkv[base], x2 = qkv[base + 1];
    qkv[base]     = x1 * cs - x2 * sn;
    qkv[base + 1] = x1 * sn + x2 * cs;
    float y1 = qkv[base + DM], y2 = qkv[base + DM + 1];
    qkv[base + DM]     = y1 * cs - y2 * sn;
    qkv[base + DM + 1] = y1 * sn + y2 * cs;
}

// ===========================================================================
// Causal flash attention (fp32 SIMT). One CTA = one (b, h, 64-row q tile).
// ===========================================================================
__global__ __launch_bounds__(256) void flash_kernel(const float* __restrict__ qkv,
                                                    float* __restrict__ o) {
    extern __shared__ float sm[];
    float* Qs = sm;
    float* Ks = sm + 64 * 68;
    float* Vs = sm + 2 * 64 * 68;
    float* Ps = sm + 3 * 64 * 68;
    int t = threadIdx.x, tx = t & 15, ty = t >> 4;
    int qt = blockIdx.x, h = blockIdx.y, b = blockIdx.z;
    int q0 = qt * 64;

    const float* qbase = qkv + ((size_t)(b * LSEQ + q0)) * 3 * DM + h * DK;
    for (int f = t; f < 1024; f += 256) {
        int row = f >> 4;
        int qd  = (f & 15) << 2;
        float4 v = *(const float4*)(qbase + (size_t)row * 3 * DM + qd);
        Qs[(qd + 0) * 68 + row] = v.x; Qs[(qd + 1) * 68 + row] = v.y;
        Qs[(qd + 2) * 68 + row] = v.z; Qs[(qd + 3) * 68 + row] = v.w;
    }

    float m[4], lsum[4], acc[4][4];
    #pragma unroll
    for (int i = 0; i < 4; i++) {
        m[i] = -1e30f; lsum[i] = 0.f;
        #pragma unroll
        for (int j = 0; j < 4; j++) acc[i][j] = 0.f;
    }

    for (int kt = 0; kt <= qt; kt++) {
        const float* kb = qkv + ((size_t)(b * LSEQ + kt * 64)) * 3 * DM + DM + h * DK;
        const float* vbp = kb + DM;
        for (int f = t; f < 1024; f += 256) {
            int row = f >> 4;
            int qd  = (f & 15) << 2;
            float4 kv4 = *(const float4*)(kb + (size_t)row * 3 * DM + qd);
            Ks[(qd + 0) * 68 + row] = kv4.x; Ks[(qd + 1) * 68 + row] = kv4.y;
            Ks[(qd + 2) * 68 + row] = kv4.z; Ks[(qd + 3) * 68 + row] = kv4.w;
            float4 vv4 = *(const float4*)(vbp + (size_t)row * 3 * DM + qd);
            *(float4*)&Vs[row * 68 + qd] = vv4;
        }
        __syncthreads();

        float s[4][4];
        #pragma unroll
        for (int i = 0; i < 4; i++)
            #pragma unroll
            for (int j = 0; j < 4; j++) s[i][j] = 0.f;
        #pragma unroll 4
        for (int d = 0; d < 64; d++) {
            float4 qa = *(float4*)&Qs[d * 68 + ty * 4];
            float4 ka = *(float4*)&Ks[d * 68 + tx * 4];
            float qv[4] = {qa.x, qa.y, qa.z, qa.w};
            float kv[4] = {ka.x, ka.y, ka.z, ka.w};
            #pragma unroll
            for (int i = 0; i < 4; i++)
                #pragma unroll
                for (int j = 0; j < 4; j++) s[i][j] += qv[i] * kv[j];
        }
        const float scale = 0.125f;
        bool diag = (kt == qt);
        #pragma unroll
        for (int i = 0; i < 4; i++)
            #pragma unroll
            for (int j = 0; j < 4; j++) {
                s[i][j] *= scale;
                if (diag && (tx * 4 + j) > (ty * 4 + i)) s[i][j] = -1e30f;
            }

        float mi[4];
        #pragma unroll
        for (int i = 0; i < 4; i++)
            mi[i] = fmaxf(fmaxf(s[i][0], s[i][1]), fmaxf(s[i][2], s[i][3]));
        #pragma unroll
        for (int off = 8; off; off >>= 1)
            #pragma unroll
            for (int i = 0; i < 4; i++)
                mi[i] = fmaxf(mi[i], __shfl_xor_sync(0xffffffffu, mi[i], off));
        float alpha[4], rs[4];
        #pragma unroll
        for (int i = 0; i < 4; i++) {
            float mn = fmaxf(m[i], mi[i]);
            alpha[i] = __expf(m[i] - mn);
            m[i] = mn;
            rs[i] = 0.f;
            #pragma unroll
            for (int j = 0; j < 4; j++) {
                s[i][j] = __expf(s[i][j] - mn);
                rs[i] += s[i][j];
            }
        }
        #pragma unroll
        for (int off = 8; off; off >>= 1)
            #pragma unroll
            for (int i = 0; i < 4; i++)
                rs[i] += __shfl_xor_sync(0xffffffffu, rs[i], off);
        #pragma unroll
        for (int i = 0; i < 4; i++) {
            lsum[i] = lsum[i] * alpha[i] + rs[i];
            #pragma unroll
            for (int j = 0; j < 4; j++) acc[i][j] *= alpha[i];
        }
        #pragma unroll
        for (int i = 0; i < 4; i++)
            #pragma unroll
            for (int j = 0; j < 4; j++)
                Ps[(tx * 4 + j) * 68 + ty * 4 + i] = s[i][j];
        __syncthreads();

        #pragma unroll 4
        for (int kk = 0; kk < 64; kk++) {
            float4 pa = *(float4*)&Ps[kk * 68 + ty * 4];
            float4 va = *(float4*)&Vs[kk * 68 + tx * 4];
            float pv[4] = {pa.x, pa.y, pa.z, pa.w};
            float vv[4] = {va.x, va.y, va.z, va.w};
            #pragma unroll
            for (int i = 0; i < 4; i++)
                #pragma unroll
                for (int j = 0; j < 4; j++) acc[i][j] += pv[i] * vv[j];
        }
        __syncthreads();
    }

    #pragma unroll
    for (int i = 0; i < 4; i++) {
        int token = b * LSEQ + q0 + ty * 4 + i;
        float inv = 1.0f / lsum[i];
        float* op = o + (size_t)token * DM + h * DK + tx * 4;
        *(float4*)op = make_float4(acc[i][0] * inv, acc[i][1] * inv,
                                   acc[i][2] * inv, acc[i][3] * inv);
    }
}

// ===========================================================================
extern "C" void kernel_launch(void* const* d_in, const int* in_sizes, int n_in,
                              void* d_out, int out_size) {
    const float* x    = (const float*)d_in[0];
    const float* W_in = (const float*)d_in[1];
    const float* W_o  = (const float*)d_in[2];
    float* out = (float*)d_out;

    float *h, *qkv, *o;
    cudaGetSymbolAddress((void**)&h,   g_h);
    cudaGetSymbolAddress((void**)&qkv, g_qkv);
    cudaGetSymbolAddress((void**)&o,   g_o);

    const int FLASH_SMEM = 4 * 64 * 68 * 4;
    cudaFuncSetAttribute(flash_kernel, cudaFuncAttributeMaxDynamicSharedMemorySize,
                         FLASH_SMEM);
    cudaFuncSetAttribute(gemm_tc, cudaFuncAttributeMaxDynamicSharedMemorySize,
                         GEMM_SMEM);

    ln_kernel<<<TOKENS, 256>>>(x, h);

    dim3 g1(3 * DM / BN, TOKENS / BM);
    gemm_tc<<<g1, 256, GEMM_SMEM>>>(h, W_in, qkv, TOKENS, 3 * DM, DM);

    rope_kernel<<<TOKENS, 512>>>(qkv);

    dim3 g2(LSEQ / 64, NH, NB);
    flash_kernel<<<g2, 256, FLASH_SMEM>>>(qkv, o);

    dim3 g3(DM / BN, TOKENS / BM);
    gemm_tc<<<g3, 256, GEMM_SMEM>>>(o, W_o, out, TOKENS, DM, DM);
}

// round 4
// speedup vs baseline: 1.3274x; 1.3274x over previous
#include <cuda_runtime.h>
#include <cuda_bf16.h>
#include <cstdint>

#define TOKENS 8192
#define DM     1024
#define LSEQ   2048
#define NB     4
#define NH     16
#define DK     64

// Scratch (device globals — no allocation in kernel_launch)
__device__ float g_h[TOKENS * DM];               // layernorm output
__device__ float g_qkv[(size_t)TOKENS * 3 * DM]; // qkv (rope applied in-place)
__device__ float g_o[TOKENS * DM];               // attention output

// ===========================================================================
// Helpers
// ===========================================================================
__device__ __forceinline__ void mma_bf16(float* c, const uint32_t* a,
                                         const uint32_t* b) {
    asm volatile(
        "mma.sync.aligned.m16n8k16.row.col.f32.bf16.bf16.f32 "
        "{%0,%1,%2,%3}, {%4,%5,%6,%7}, {%8,%9}, {%0,%1,%2,%3};\n"
        : "+f"(c[0]), "+f"(c[1]), "+f"(c[2]), "+f"(c[3])
        : "r"(a[0]), "r"(a[1]), "r"(a[2]), "r"(a[3]), "r"(b[0]), "r"(b[1]));
}
__device__ __forceinline__ uint32_t pack2(__nv_bfloat16 lo, __nv_bfloat16 hi) {
    __nv_bfloat162 t = __halves2bfloat162(lo, hi);  // .x = lo half (bits 0..15)
    return *reinterpret_cast<uint32_t*>(&t);
}

// ===========================================================================
// LayerNorm: one block per row (1024 floats), 256 threads x float4
// ===========================================================================
__global__ __launch_bounds__(256) void ln_kernel(const float* __restrict__ x,
                                                 float* __restrict__ h) {
    int row = blockIdx.x;
    int t = threadIdx.x;
    const float4* xr = (const float4*)(x + (size_t)row * DM);
    float4 v = xr[t];
    float s  = v.x + v.y + v.z + v.w;
    float ss = v.x * v.x + v.y * v.y + v.z * v.z + v.w * v.w;
    #pragma unroll
    for (int off = 16; off; off >>= 1) {
        s  += __shfl_xor_sync(0xffffffffu, s, off);
        ss += __shfl_xor_sync(0xffffffffu, ss, off);
    }
    __shared__ float sh[16];
    __shared__ float sh_mu, sh_r;
    int warp = t >> 5, lane = t & 31;
    if (lane == 0) { sh[warp] = s; sh[warp + 8] = ss; }
    __syncthreads();
    if (t == 0) {
        float S = 0.f, SS = 0.f;
        #pragma unroll
        for (int w = 0; w < 8; w++) { S += sh[w]; SS += sh[w + 8]; }
        float mu  = S * (1.0f / DM);
        float var = SS * (1.0f / DM) - mu * mu;
        sh_mu = mu;
        sh_r  = rsqrtf(var + 1e-8f);
    }
    __syncthreads();
    float mu = sh_mu, r = sh_r;
    float4 o = make_float4((v.x - mu) * r, (v.y - mu) * r,
                           (v.z - mu) * r, (v.w - mu) * r);
    ((float4*)(h + (size_t)row * DM))[t] = o;
}

// ===========================================================================
// Split-bf16 mma.sync NT GEMM: C[M,N] = A[M,K] * B[N,K]^T, fp32 in/out.
// 128x128 CTA tile, BK=16 (one m16n8k16 step), 8 warps (2x4), warp tile
// 64x32. hi/lo bf16 decomposition, 3 products -> rel err ~2e-5.
// Smem: packed bf16x2 words, row stride 12 u32 (conflict-free), double buffer.
// ===========================================================================
#define BM 128
#define BN 128
#define SROW 12                        // u32 per row (8 data + 4 pad)
#define SARR (BM * SROW)               // 1536 u32 per array
#define SSTAGE (4 * SARR)              // Ahi, Alo, Bhi, Blo
#define GEMM_SMEM (2 * SSTAGE * 4)     // 49152 bytes

__global__ __launch_bounds__(256) void gemm_tc(const float* __restrict__ A,
                                               const float* __restrict__ B,
                                               float* __restrict__ C,
                                               int M, int N_, int K) {
    extern __shared__ uint32_t smu[];
    int t = threadIdx.x;
    int lane = t & 31, wid = t >> 5;
    int wm = wid >> 2, wn = wid & 3;      // 2 x 4 warp grid
    int g = lane >> 2, t4 = lane & 3;
    int m0 = blockIdx.y * BM, n0 = blockIdx.x * BN;

    float acc[4][4][4];
    #pragma unroll
    for (int i = 0; i < 4; i++)
        #pragma unroll
        for (int j = 0; j < 4; j++)
            #pragma unroll
            for (int q = 0; q < 4; q++) acc[i][j][q] = 0.f;

    // global-load indexing: 512 float4 per matrix per stage; thread does 2
    int r0 = t >> 2, q4 = (t & 3) * 4;    // rows 0..63 / k-offset 0,4,8,12
    int q2 = (t & 3) * 2;                 // u32 word index

    const int NSTAGE = K / 16;
    float4 pa0, pa1, pb0, pb1;
    {
        const float* Ab = A + (size_t)m0 * K;
        const float* Bb = B + (size_t)n0 * K;
        pa0 = *(const float4*)(Ab + (size_t)r0 * K + q4);
        pa1 = *(const float4*)(Ab + (size_t)(r0 + 64) * K + q4);
        pb0 = *(const float4*)(Bb + (size_t)r0 * K + q4);
        pb1 = *(const float4*)(Bb + (size_t)(r0 + 64) * K + q4);
    }

    for (int sidx = 0; sidx < NSTAGE; sidx++) {
        uint32_t* Sb  = smu + (sidx & 1) * SSTAGE;
        uint32_t* Ahi = Sb;
        uint32_t* Alo = Sb + SARR;
        uint32_t* Bhi = Sb + 2 * SARR;
        uint32_t* Blo = Sb + 3 * SARR;

        // split + store prefetched stage
        {
            float4 vv[4] = {pa0, pa1, pb0, pb1};
            uint32_t* dsthi[4] = {Ahi, Ahi, Bhi, Bhi};
            uint32_t* dstlo[4] = {Alo, Alo, Blo, Blo};
            int rows[4] = {r0, r0 + 64, r0, r0 + 64};
            #pragma unroll
            for (int p = 0; p < 4; p++) {
                float4 v = vv[p];
                __nv_bfloat16 hx = __float2bfloat16_rn(v.x);
                __nv_bfloat16 hy = __float2bfloat16_rn(v.y);
                __nv_bfloat16 hz = __float2bfloat16_rn(v.z);
                __nv_bfloat16 hw = __float2bfloat16_rn(v.w);
                float lx = v.x - __bfloat162float(hx);
                float ly = v.y - __bfloat162float(hy);
                float lz = v.z - __bfloat162float(hz);
                float lw = v.w - __bfloat162float(hw);
                int idx = rows[p] * SROW + q2;
                dsthi[p][idx]     = pack2(hx, hy);
                dsthi[p][idx + 1] = pack2(hz, hw);
                dstlo[p][idx]     = pack2(__float2bfloat16_rn(lx),
                                          __float2bfloat16_rn(ly));
                dstlo[p][idx + 1] = pack2(__float2bfloat16_rn(lz),
                                          __float2bfloat16_rn(lw));
            }
        }
        __syncthreads();

        // prefetch next stage
        if (sidx + 1 < NSTAGE) {
            int k0 = (sidx + 1) * 16;
            const float* Ab = A + (size_t)m0 * K + k0;
            const float* Bb = B + (size_t)n0 * K + k0;
            pa0 = *(const float4*)(Ab + (size_t)r0 * K + q4);
            pa1 = *(const float4*)(Ab + (size_t)(r0 + 64) * K + q4);
            pb0 = *(const float4*)(Bb + (size_t)r0 * K + q4);
            pb1 = *(const float4*)(Bb + (size_t)(r0 + 64) * K + q4);
        }

        // fragments + 48 mma
        uint32_t ah[4][4], al[4][4], bh[4][2], bl[4][2];
        #pragma unroll
        for (int mb = 0; mb < 4; mb++) {
            int idx = (wm * 64 + mb * 16 + g) * SROW + t4;
            ah[mb][0] = Ahi[idx];       ah[mb][1] = Ahi[idx + 8 * SROW];
            ah[mb][2] = Ahi[idx + 4];   ah[mb][3] = Ahi[idx + 8 * SROW + 4];
            al[mb][0] = Alo[idx];       al[mb][1] = Alo[idx + 8 * SROW];
            al[mb][2] = Alo[idx + 4];   al[mb][3] = Alo[idx + 8 * SROW + 4];
        }
        #pragma unroll
        for (int nb = 0; nb < 4; nb++) {
            int idx = (wn * 32 + nb * 8 + g) * SROW + t4;
            bh[nb][0] = Bhi[idx];  bh[nb][1] = Bhi[idx + 4];
            bl[nb][0] = Blo[idx];  bl[nb][1] = Blo[idx + 4];
        }
        #pragma unroll
        for (int mb = 0; mb < 4; mb++)
            #pragma unroll
            for (int nb = 0; nb < 4; nb++) {
                mma_bf16(acc[mb][nb], ah[mb], bh[nb]);
                mma_bf16(acc[mb][nb], ah[mb], bl[nb]);
                mma_bf16(acc[mb][nb], al[mb], bh[nb]);
            }
        __syncthreads();
    }

    // epilogue: c0,c1 -> (g, 2*t4), c2,c3 -> (g+8, 2*t4)
    #pragma unroll
    for (int mb = 0; mb < 4; mb++) {
        int row = m0 + wm * 64 + mb * 16 + g;
        #pragma unroll
        for (int nb = 0; nb < 4; nb++) {
            int col = n0 + wn * 32 + nb * 8 + 2 * t4;
            *(float2*)(C + (size_t)row * N_ + col) =
                make_float2(acc[mb][nb][0], acc[mb][nb][1]);
            *(float2*)(C + (size_t)(row + 8) * N_ + col) =
                make_float2(acc[mb][nb][2], acc[mb][nb][3]);
        }
    }
}

// ===========================================================================
// RoPE (interleaved) applied in-place to q and k slices of g_qkv.
// ===========================================================================
__global__ __launch_bounds__(512) void rope_kernel(float* __restrict__ qkv) {
    int token = blockIdx.x;
    int p = threadIdx.x;
    int head = p >> 5;
    int i = p & 31;
    int l = token & (LSEQ - 1);
    double inv = pow(10000.0, -(double)i / 32.0);
    double ang = (double)l * inv;
    double snd, csd;
    sincos(ang, &snd, &csd);
    float sn = (float)snd, cs = (float)csd;
    size_t base = (size_t)token * 3 * DM + head * DK + 2 * i;
    float x1 = qkv[base], x2 = qkv[base + 1];
    qkv[base]     = x1 * cs - x2 * sn;
    qkv[base + 1] = x1 * sn + x2 * cs;
    float y1 = qkv[base + DM], y2 = qkv[base + DM + 1];
    qkv[base + DM]     = y1 * cs - y2 * sn;
    qkv[base + DM + 1] = y1 * sn + y2 * cs;
}

// ===========================================================================
// Causal flash attention (fp32 SIMT). One CTA = one (b, h, 64-row q tile).
// ===========================================================================
__global__ __launch_bounds__(256) void flash_kernel(const float* __restrict__ qkv,
                                                    float* __restrict__ o) {
    extern __shared__ float sm[];
    float* Qs = sm;
    float* Ks = sm + 64 * 68;
    float* Vs = sm + 2 * 64 * 68;
    float* Ps = sm + 3 * 64 * 68;
    int t = threadIdx.x, tx = t & 15, ty = t >> 4;
    int qt = blockIdx.x, h = blockIdx.y, b = blockIdx.z;
    int q0 = qt * 64;

    const float* qbase = qkv + ((size_t)(b * LSEQ + q0)) * 3 * DM + h * DK;
    for (int f = t; f < 1024; f += 256) {
        int row = f >> 4;
        int qd  = (f & 15) << 2;
        float4 v = *(const float4*)(qbase + (size_t)row * 3 * DM + qd);
        Qs[(qd + 0) * 68 + row] = v.x; Qs[(qd + 1) * 68 + row] = v.y;
        Qs[(qd + 2) * 68 + row] = v.z; Qs[(qd + 3) * 68 + row] = v.w;
    }

    float m[4], lsum[4], acc[4][4];
    #pragma unroll
    for (int i = 0; i < 4; i++) {
        m[i] = -1e30f; lsum[i] = 0.f;
        #pragma unroll
        for (int j = 0; j < 4; j++) acc[i][j] = 0.f;
    }

    for (int kt = 0; kt <= qt; kt++) {
        const float* kb = qkv + ((size_t)(b * LSEQ + kt * 64)) * 3 * DM + DM + h * DK;
        const float* vbp = kb + DM;
        for (int f = t; f < 1024; f += 256) {
            int row = f >> 4;
            int qd  = (f & 15) << 2;
            float4 kv4 = *(const float4*)(kb + (size_t)row * 3 * DM + qd);
            Ks[(qd + 0) * 68 + row] = kv4.x; Ks[(qd + 1) * 68 + row] = kv4.y;
            Ks[(qd + 2) * 68 + row] = kv4.z; Ks[(qd + 3) * 68 + row] = kv4.w;
            float4 vv4 = *(const float4*)(vbp + (size_t)row * 3 * DM + qd);
            *(float4*)&Vs[row * 68 + qd] = vv4;
        }
        __syncthreads();

        float s[4][4];
        #pragma unroll
        for (int i = 0; i < 4; i++)
            #pragma unroll
            for (int j = 0; j < 4; j++) s[i][j] = 0.f;
        #pragma unroll 4
        for (int d = 0; d < 64; d++) {
            float4 qa = *(float4*)&Qs[d * 68 + ty * 4];
            float4 ka = *(float4*)&Ks[d * 68 + tx * 4];
            float qv[4] = {qa.x, qa.y, qa.z, qa.w};
            float kv[4] = {ka.x, ka.y, ka.z, ka.w};
            #pragma unroll
            for (int i = 0; i < 4; i++)
                #pragma unroll
                for (int j = 0; j < 4; j++) s[i][j] += qv[i] * kv[j];
        }
        const float scale = 0.125f;
        bool diag = (kt == qt);
        #pragma unroll
        for (int i = 0; i < 4; i++)
            #pragma unroll
            for (int j = 0; j < 4; j++) {
                s[i][j] *= scale;
                if (diag && (tx * 4 + j) > (ty * 4 + i)) s[i][j] = -1e30f;
            }

        float mi[4];
        #pragma unroll
        for (int i = 0; i < 4; i++)
            mi[i] = fmaxf(fmaxf(s[i][0], s[i][1]), fmaxf(s[i][2], s[i][3]));
        #pragma unroll
        for (int off = 8; off; off >>= 1)
            #pragma unroll
            for (int i = 0; i < 4; i++)
                mi[i] = fmaxf(mi[i], __shfl_xor_sync(0xffffffffu, mi[i], off));
        float alpha[4], rs[4];
        #pragma unroll
        for (int i = 0; i < 4; i++) {
            float mn = fmaxf(m[i], mi[i]);
            alpha[i] = __expf(m[i] - mn);
            m[i] = mn;
            rs[i] = 0.f;
            #pragma unroll
            for (int j = 0; j < 4; j++) {
                s[i][j] = __expf(s[i][j] - mn);
                rs[i] += s[i][j];
            }
        }
        #pragma unroll
        for (int off = 8; off; off >>= 1)
            #pragma unroll
            for (int i = 0; i < 4; i++)
                rs[i] += __shfl_xor_sync(0xffffffffu, rs[i], off);
        #pragma unroll
        for (int i = 0; i < 4; i++) {
            lsum[i] = lsum[i] * alpha[i] + rs[i];
            #pragma unroll
            for (int j = 0; j < 4; j++) acc[i][j] *= alpha[i];
        }
        #pragma unroll
        for (int i = 0; i < 4; i++)
            #pragma unroll
            for (int j = 0; j < 4; j++)
                Ps[(tx * 4 + j) * 68 + ty * 4 + i] = s[i][j];
        __syncthreads();

        #pragma unroll 4
        for (int kk = 0; kk < 64; kk++) {
            float4 pa = *(float4*)&Ps[kk * 68 + ty * 4];
            float4 va = *(float4*)&Vs[kk * 68 + tx * 4];
            float pv[4] = {pa.x, pa.y, pa.z, pa.w};
            float vv[4] = {va.x, va.y, va.z, va.w};
            #pragma unroll
            for (int i = 0; i < 4; i++)
                #pragma unroll
                for (int j = 0; j < 4; j++) acc[i][j] += pv[i] * vv[j];
        }
        __syncthreads();
    }

    #pragma unroll
    for (int i = 0; i < 4; i++) {
        int token = b * LSEQ + q0 + ty * 4 + i;
        float inv = 1.0f / lsum[i];
        float* op = o + (size_t)token * DM + h * DK + tx * 4;
        *(float4*)op = make_float4(acc[i][0] * inv, acc[i][1] * inv,
                                   acc[i][2] * inv, acc[i][3] * inv);
    }
}

// ===========================================================================
extern "C" void kernel_launch(void* const* d_in, const int* in_sizes, int n_in,
                              void* d_out, int out_size) {
    const float* x    = (const float*)d_in[0];
    const float* W_in = (const float*)d_in[1];
    const float* W_o  = (const float*)d_in[2];
    float* out = (float*)d_out;

    float *h, *qkv, *o;
    cudaGetSymbolAddress((void**)&h,   g_h);
    cudaGetSymbolAddress((void**)&qkv, g_qkv);
    cudaGetSymbolAddress((void**)&o,   g_o);

    const int FLASH_SMEM = 4 * 64 * 68 * 4;
    cudaFuncSetAttribute(flash_kernel, cudaFuncAttributeMaxDynamicSharedMemorySize,
                         FLASH_SMEM);
    cudaFuncSetAttribute(gemm_tc, cudaFuncAttributeMaxDynamicSharedMemorySize,
                         GEMM_SMEM);

    ln_kernel<<<TOKENS, 256>>>(x, h);

    dim3 g1(3 * DM / BN, TOKENS / BM);
    gemm_tc<<<g1, 256, GEMM_SMEM>>>(h, W_in, qkv, TOKENS, 3 * DM, DM);

    rope_kernel<<<TOKENS, 512>>>(qkv);

    dim3 g2(LSEQ / 64, NH, NB);
    flash_kernel<<<g2, 256, FLASH_SMEM>>>(qkv, o);

    dim3 g3(DM / BN, TOKENS / BM);
    gemm_tc<<<g3, 256, GEMM_SMEM>>>(o, W_o, out, TOKENS, DM, DM);
}

// round 5
// speedup vs baseline: 1.8433x; 1.3887x over previous
#include <cuda_runtime.h>
#include <cuda_bf16.h>
#include <cstdint>

#define TOKENS 8192
#define DM     1024
#define LSEQ   2048
#define NB     4
#define NH     16
#define DK     64

// Scratch (device globals — no allocation in kernel_launch)
__device__ float g_h[TOKENS * DM];               // layernorm output
__device__ float g_qkv[(size_t)TOKENS * 3 * DM]; // qkv (rope applied in-place)
__device__ float g_o[TOKENS * DM];               // attention output

// ===========================================================================
// Helpers
// ===========================================================================
__device__ __forceinline__ void mma_bf16(float* c, const uint32_t* a,
                                         const uint32_t* b) {
    asm volatile(
        "mma.sync.aligned.m16n8k16.row.col.f32.bf16.bf16.f32 "
        "{%0,%1,%2,%3}, {%4,%5,%6,%7}, {%8,%9}, {%0,%1,%2,%3};\n"
        : "+f"(c[0]), "+f"(c[1]), "+f"(c[2]), "+f"(c[3])
        : "r"(a[0]), "r"(a[1]), "r"(a[2]), "r"(a[3]), "r"(b[0]), "r"(b[1]));
}
__device__ __forceinline__ uint32_t pack2(__nv_bfloat16 lo, __nv_bfloat16 hi) {
    __nv_bfloat162 t = __halves2bfloat162(lo, hi);  // .x = bits 0..15
    return *reinterpret_cast<uint32_t*>(&t);
}
__device__ __forceinline__ uint32_t smem_u32addr(const void* p) {
    uint32_t a;
    asm("{ .reg .u64 t; cvta.to.shared.u64 t, %1; cvt.u32.u64 %0, t; }"
        : "=r"(a) : "l"(p));
    return a;
}
__device__ __forceinline__ void ldmx4t(uint32_t& r0, uint32_t& r1,
                                       uint32_t& r2, uint32_t& r3,
                                       uint32_t addr) {
    asm volatile(
        "ldmatrix.sync.aligned.m8n8.x4.trans.shared.b16 {%0,%1,%2,%3}, [%4];"
        : "=r"(r0), "=r"(r1), "=r"(r2), "=r"(r3) : "r"(addr));
}
// split fp32 -> (hi, lo) bf16 pair packed as two u32 words per float4
__device__ __forceinline__ void split4(float4 v, uint32_t& h0, uint32_t& h1,
                                       uint32_t& l0, uint32_t& l1) {
    __nv_bfloat16 hx = __float2bfloat16_rn(v.x);
    __nv_bfloat16 hy = __float2bfloat16_rn(v.y);
    __nv_bfloat16 hz = __float2bfloat16_rn(v.z);
    __nv_bfloat16 hw = __float2bfloat16_rn(v.w);
    h0 = pack2(hx, hy); h1 = pack2(hz, hw);
    l0 = pack2(__float2bfloat16_rn(v.x - __bfloat162float(hx)),
               __float2bfloat16_rn(v.y - __bfloat162float(hy)));
    l1 = pack2(__float2bfloat16_rn(v.z - __bfloat162float(hz)),
               __float2bfloat16_rn(v.w - __bfloat162float(hw)));
}

// ===========================================================================
// LayerNorm
// ===========================================================================
__global__ __launch_bounds__(256) void ln_kernel(const float* __restrict__ x,
                                                 float* __restrict__ h) {
    int row = blockIdx.x;
    int t = threadIdx.x;
    const float4* xr = (const float4*)(x + (size_t)row * DM);
    float4 v = xr[t];
    float s  = v.x + v.y + v.z + v.w;
    float ss = v.x * v.x + v.y * v.y + v.z * v.z + v.w * v.w;
    #pragma unroll
    for (int off = 16; off; off >>= 1) {
        s  += __shfl_xor_sync(0xffffffffu, s, off);
        ss += __shfl_xor_sync(0xffffffffu, ss, off);
    }
    __shared__ float sh[16];
    __shared__ float sh_mu, sh_r;
    int warp = t >> 5, lane = t & 31;
    if (lane == 0) { sh[warp] = s; sh[warp + 8] = ss; }
    __syncthreads();
    if (t == 0) {
        float S = 0.f, SS = 0.f;
        #pragma unroll
        for (int w = 0; w < 8; w++) { S += sh[w]; SS += sh[w + 8]; }
        float mu  = S * (1.0f / DM);
        float var = SS * (1.0f / DM) - mu * mu;
        sh_mu = mu;
        sh_r  = rsqrtf(var + 1e-8f);
    }
    __syncthreads();
    float mu = sh_mu, r = sh_r;
    float4 o = make_float4((v.x - mu) * r, (v.y - mu) * r,
                           (v.z - mu) * r, (v.w - mu) * r);
    ((float4*)(h + (size_t)row * DM))[t] = o;
}

// ===========================================================================
// Split-bf16 mma.sync NT GEMM (unchanged from R4)
// ===========================================================================
#define BM 128
#define BN 128
#define SROW 12
#define SARR (BM * SROW)
#define SSTAGE (4 * SARR)
#define GEMM_SMEM (2 * SSTAGE * 4)

__global__ __launch_bounds__(256) void gemm_tc(const float* __restrict__ A,
                                               const float* __restrict__ B,
                                               float* __restrict__ C,
                                               int M, int N_, int K) {
    extern __shared__ uint32_t smu[];
    int t = threadIdx.x;
    int lane = t & 31, wid = t >> 5;
    int wm = wid >> 2, wn = wid & 3;
    int g = lane >> 2, t4 = lane & 3;
    int m0 = blockIdx.y * BM, n0 = blockIdx.x * BN;

    float acc[4][4][4];
    #pragma unroll
    for (int i = 0; i < 4; i++)
        #pragma unroll
        for (int j = 0; j < 4; j++)
            #pragma unroll
            for (int q = 0; q < 4; q++) acc[i][j][q] = 0.f;

    int r0 = t >> 2, q4 = (t & 3) * 4;
    int q2 = (t & 3) * 2;

    const int NSTAGE = K / 16;
    float4 pa0, pa1, pb0, pb1;
    {
        const float* Ab = A + (size_t)m0 * K;
        const float* Bb = B + (size_t)n0 * K;
        pa0 = *(const float4*)(Ab + (size_t)r0 * K + q4);
        pa1 = *(const float4*)(Ab + (size_t)(r0 + 64) * K + q4);
        pb0 = *(const float4*)(Bb + (size_t)r0 * K + q4);
        pb1 = *(const float4*)(Bb + (size_t)(r0 + 64) * K + q4);
    }

    for (int sidx = 0; sidx < NSTAGE; sidx++) {
        uint32_t* Sb  = smu + (sidx & 1) * SSTAGE;
        uint32_t* Ahi = Sb;
        uint32_t* Alo = Sb + SARR;
        uint32_t* Bhi = Sb + 2 * SARR;
        uint32_t* Blo = Sb + 3 * SARR;

        {
            uint32_t h0, h1, l0, l1;
            split4(pa0, h0, h1, l0, l1);
            Ahi[r0 * SROW + q2] = h0; Ahi[r0 * SROW + q2 + 1] = h1;
            Alo[r0 * SROW + q2] = l0; Alo[r0 * SROW + q2 + 1] = l1;
            split4(pa1, h0, h1, l0, l1);
            Ahi[(r0 + 64) * SROW + q2] = h0; Ahi[(r0 + 64) * SROW + q2 + 1] = h1;
            Alo[(r0 + 64) * SROW + q2] = l0; Alo[(r0 + 64) * SROW + q2 + 1] = l1;
            split4(pb0, h0, h1, l0, l1);
            Bhi[r0 * SROW + q2] = h0; Bhi[r0 * SROW + q2 + 1] = h1;
            Blo[r0 * SROW + q2] = l0; Blo[r0 * SROW + q2 + 1] = l1;
            split4(pb1, h0, h1, l0, l1);
            Bhi[(r0 + 64) * SROW + q2] = h0; Bhi[(r0 + 64) * SROW + q2 + 1] = h1;
            Blo[(r0 + 64) * SROW + q2] = l0; Blo[(r0 + 64) * SROW + q2 + 1] = l1;
        }
        __syncthreads();

        if (sidx + 1 < NSTAGE) {
            int k0 = (sidx + 1) * 16;
            const float* Ab = A + (size_t)m0 * K + k0;
            const float* Bb = B + (size_t)n0 * K + k0;
            pa0 = *(const float4*)(Ab + (size_t)r0 * K + q4);
            pa1 = *(const float4*)(Ab + (size_t)(r0 + 64) * K + q4);
            pb0 = *(const float4*)(Bb + (size_t)r0 * K + q4);
            pb1 = *(const float4*)(Bb + (size_t)(r0 + 64) * K + q4);
        }

        uint32_t ah[4][4], al[4][4], bh[4][2], bl[4][2];
        #pragma unroll
        for (int mb = 0; mb < 4; mb++) {
            int idx = (wm * 64 + mb * 16 + g) * SROW + t4;
            ah[mb][0] = Ahi[idx];       ah[mb][1] = Ahi[idx + 8 * SROW];
            ah[mb][2] = Ahi[idx + 4];   ah[mb][3] = Ahi[idx + 8 * SROW + 4];
            al[mb][0] = Alo[idx];       al[mb][1] = Alo[idx + 8 * SROW];
            al[mb][2] = Alo[idx + 4];   al[mb][3] = Alo[idx + 8 * SROW + 4];
        }
        #pragma unroll
        for (int nb = 0; nb < 4; nb++) {
            int idx = (wn * 32 + nb * 8 + g) * SROW + t4;
            bh[nb][0] = Bhi[idx];  bh[nb][1] = Bhi[idx + 4];
            bl[nb][0] = Blo[idx];  bl[nb][1] = Blo[idx + 4];
        }
        #pragma unroll
        for (int mb = 0; mb < 4; mb++)
            #pragma unroll
            for (int nb = 0; nb < 4; nb++) {
                mma_bf16(acc[mb][nb], ah[mb], bh[nb]);
                mma_bf16(acc[mb][nb], ah[mb], bl[nb]);
                mma_bf16(acc[mb][nb], al[mb], bh[nb]);
            }
        __syncthreads();
    }

    #pragma unroll
    for (int mb = 0; mb < 4; mb++) {
        int row = m0 + wm * 64 + mb * 16 + g;
        #pragma unroll
        for (int nb = 0; nb < 4; nb++) {
            int col = n0 + wn * 32 + nb * 8 + 2 * t4;
            *(float2*)(C + (size_t)row * N_ + col) =
                make_float2(acc[mb][nb][0], acc[mb][nb][1]);
            *(float2*)(C + (size_t)(row + 8) * N_ + col) =
                make_float2(acc[mb][nb][2], acc[mb][nb][3]);
        }
    }
}

// ===========================================================================
// RoPE (unchanged)
// ===========================================================================
__global__ __launch_bounds__(512) void rope_kernel(float* __restrict__ qkv) {
    int token = blockIdx.x;
    int p = threadIdx.x;
    int head = p >> 5;
    int i = p & 31;
    int l = token & (LSEQ - 1);
    double inv = pow(10000.0, -(double)i / 32.0);
    double ang = (double)l * inv;
    double snd, csd;
    sincos(ang, &snd, &csd);
    float sn = (float)snd, cs = (float)csd;
    size_t base = (size_t)token * 3 * DM + head * DK + 2 * i;
    float x1 = qkv[base], x2 = qkv[base + 1];
    qkv[base]     = x1 * cs - x2 * sn;
    qkv[base + 1] = x1 * sn + x2 * cs;
    float y1 = qkv[base + DM], y2 = qkv[base + DM + 1];
    qkv[base + DM]     = y1 * cs - y2 * sn;
    qkv[base + DM + 1] = y1 * sn + y2 * cs;
}

// ===========================================================================
// Tensor-core causal flash attention (split-bf16 mma.sync, FA2-style).
// CTA: 128 q-rows x (b,h). 8 warps, warp w owns q rows [16w, 16w+16).
// K tiles of 64 keys. Q/K hi-lo in smem (36-u32 row stride, conflict-free),
// V row-major bf16 hi/lo loaded via ldmatrix.x4.trans.
// ===========================================================================
#define FQ 128                 // q rows per CTA
#define FK 64                  // keys per tile
#define FR 36                  // u32 row stride
#define OQH 0
#define OQL (FQ * FR)          // 4608
#define OKH (2 * FQ * FR)      // 9216
#define OKL (OKH + FK * FR)
#define OVH (OKH + 2 * FK * FR)
#define OVL (OVH + FK * FR)
#define FLASH_SMEM ((2 * FQ * FR + 4 * FK * FR) * 4)   // 73728 B

__global__ __launch_bounds__(256) void flash_tc(const float* __restrict__ qkv,
                                                float* __restrict__ o) {
    extern __shared__ uint32_t su[];
    int t = threadIdx.x;
    int lane = t & 31, wq = t >> 5;
    int g = lane >> 2, t4 = lane & 3;
    int qt = (int)gridDim.x - 1 - (int)blockIdx.x;   // heavy tiles first
    int h = blockIdx.y, b = blockIdx.z;
    int qbase = qt * FQ;

    // ---- load Q tile (128 x 64) -> smem hi/lo ----
    {
        const float* qb = qkv + ((size_t)(b * LSEQ + qbase)) * 3 * DM + h * DK;
        #pragma unroll
        for (int it = 0; it < 8; it++) {
            int f = t + it * 256;
            int row = f >> 4, c4 = (f & 15);
            float4 v = *(const float4*)(qb + (size_t)row * 3 * DM + c4 * 4);
            uint32_t h0, h1, l0, l1;
            split4(v, h0, h1, l0, l1);
            int idx = row * FR + c4 * 2;
            su[OQH + idx] = h0; su[OQH + idx + 1] = h1;
            su[OQL + idx] = l0; su[OQL + idx + 1] = l1;
        }
    }
    __syncthreads();

    // ---- per-warp Q a-frags (kept in registers for whole kernel) ----
    uint32_t qah[4][4], qal[4][4];
    #pragma unroll
    for (int s = 0; s < 4; s++) {
        int idx = (wq * 16 + g) * FR + 8 * s + t4;
        qah[s][0] = su[OQH + idx];          qah[s][1] = su[OQH + idx + 8 * FR];
        qah[s][2] = su[OQH + idx + 4];      qah[s][3] = su[OQH + idx + 8 * FR + 4];
        qal[s][0] = su[OQL + idx];          qal[s][1] = su[OQL + idx + 8 * FR];
        qal[s][2] = su[OQL + idx + 4];      qal[s][3] = su[OQL + idx + 8 * FR + 4];
    }

    float of[8][4];
    #pragma unroll
    for (int n = 0; n < 8; n++)
        #pragma unroll
        for (int c = 0; c < 4; c++) of[n][c] = 0.f;
    float m0 = -1e30f, m1 = -1e30f, l0 = 0.f, l1 = 0.f;

    uint32_t vbase_h = smem_u32addr(su + OVH);
    uint32_t vbase_l = smem_u32addr(su + OVL);
    int voff = ((lane & 15) * FR + (lane >> 4) * 4) * 4;  // byte offset per lane

    int row0 = qbase + wq * 16 + g;          // lane's first q row
    int nkt = 2 * qt + 2;                    // kt tiles: 0 .. 2qt+1

    for (int kt = 0; kt < nkt; kt++) {
        // ---- stage K,V tile (64 x 64) ----
        {
            const float* kb = qkv + ((size_t)(b * LSEQ + kt * FK)) * 3 * DM + DM + h * DK;
            #pragma unroll
            for (int it = 0; it < 4; it++) {
                int f = t + it * 256;
                int row = f >> 4, c4 = (f & 15);
                int idx = row * FR + c4 * 2;
                float4 kv = *(const float4*)(kb + (size_t)row * 3 * DM + c4 * 4);
                uint32_t h0, h1, lo0, lo1;
                split4(kv, h0, h1, lo0, lo1);
                su[OKH + idx] = h0; su[OKH + idx + 1] = h1;
                su[OKL + idx] = lo0; su[OKL + idx + 1] = lo1;
                float4 vv = *(const float4*)(kb + DM + (size_t)row * 3 * DM + c4 * 4);
                split4(vv, h0, h1, lo0, lo1);
                su[OVH + idx] = h0; su[OVH + idx + 1] = h1;
                su[OVL + idx] = lo0; su[OVL + idx + 1] = lo1;
            }
        }
        __syncthreads();

        int ktb = kt * FK;
        bool active = (ktb <= qbase + wq * 16);   // warp-level causal skip
        if (active) {
            // ---- S = Q K^T (split bf16) ----
            float sf[8][4];
            #pragma unroll
            for (int j = 0; j < 8; j++)
                #pragma unroll
                for (int c = 0; c < 4; c++) sf[j][c] = 0.f;
            #pragma unroll
            for (int s = 0; s < 4; s++) {
                #pragma unroll
                for (int j = 0; j < 8; j++) {
                    int idx = (8 * j + g) * FR + 8 * s + t4;
                    uint32_t kb2[2], kl2[2];
                    kb2[0] = su[OKH + idx]; kb2[1] = su[OKH + idx + 4];
                    kl2[0] = su[OKL + idx]; kl2[1] = su[OKL + idx + 4];
                    mma_bf16(sf[j], qah[s], kb2);
                    mma_bf16(sf[j], qal[s], kb2);
                    mma_bf16(sf[j], qah[s], kl2);
                }
            }

            // ---- scale + causal mask ----
            const float scale = 0.125f;
            bool need_mask = (ktb + FK - 1 > qbase + wq * 16);
            #pragma unroll
            for (int j = 0; j < 8; j++) {
                int col = ktb + 8 * j + 2 * t4;
                #pragma unroll
                for (int c = 0; c < 4; c++) {
                    float v = sf[j][c] * scale;
                    if (need_mask) {
                        int cc = col + (c & 1);
                        int rr = row0 + (c >> 1) * 8;
                        if (cc > rr) v = -1e30f;
                    }
                    sf[j][c] = v;
                }
            }

            // ---- streaming softmax (rows g / g+8; quad reduction) ----
            float mx0 = -1e30f, mx1 = -1e30f;
            #pragma unroll
            for (int j = 0; j < 8; j++) {
                mx0 = fmaxf(mx0, fmaxf(sf[j][0], sf[j][1]));
                mx1 = fmaxf(mx1, fmaxf(sf[j][2], sf[j][3]));
            }
            mx0 = fmaxf(mx0, __shfl_xor_sync(0xffffffffu, mx0, 1));
            mx0 = fmaxf(mx0, __shfl_xor_sync(0xffffffffu, mx0, 2));
            mx1 = fmaxf(mx1, __shfl_xor_sync(0xffffffffu, mx1, 1));
            mx1 = fmaxf(mx1, __shfl_xor_sync(0xffffffffu, mx1, 2));
            float mn0 = fmaxf(m0, mx0), mn1 = fmaxf(m1, mx1);
            float a0 = __expf(m0 - mn0), a1 = __expf(m1 - mn1);
            m0 = mn0; m1 = mn1;
            float s0 = 0.f, s1 = 0.f;
            #pragma unroll
            for (int j = 0; j < 8; j++) {
                sf[j][0] = __expf(sf[j][0] - m0);
                sf[j][1] = __expf(sf[j][1] - m0);
                sf[j][2] = __expf(sf[j][2] - m1);
                sf[j][3] = __expf(sf[j][3] - m1);
                s0 += sf[j][0] + sf[j][1];
                s1 += sf[j][2] + sf[j][3];
            }
            s0 += __shfl_xor_sync(0xffffffffu, s0, 1);
            s0 += __shfl_xor_sync(0xffffffffu, s0, 2);
            s1 += __shfl_xor_sync(0xffffffffu, s1, 1);
            s1 += __shfl_xor_sync(0xffffffffu, s1, 2);
            l0 = l0 * a0 + s0;
            l1 = l1 * a1 + s1;
            #pragma unroll
            for (int n = 0; n < 8; n++) {
                of[n][0] *= a0; of[n][1] *= a0;
                of[n][2] *= a1; of[n][3] *= a1;
            }

            // ---- O += P V  (P from registers, V via ldmatrix.trans) ----
            #pragma unroll
            for (int s = 0; s < 4; s++) {
                // P a-frags hi/lo from S frags 2s, 2s+1
                uint32_t pah[4], pal[4];
                #pragma unroll
                for (int half = 0; half < 2; half++) {
                    float p0 = sf[2 * s + half][0], p1 = sf[2 * s + half][1];
                    float p2 = sf[2 * s + half][2], p3 = sf[2 * s + half][3];
                    __nv_bfloat16 h0 = __float2bfloat16_rn(p0);
                    __nv_bfloat16 h1b = __float2bfloat16_rn(p1);
                    __nv_bfloat16 h2 = __float2bfloat16_rn(p2);
                    __nv_bfloat16 h3 = __float2bfloat16_rn(p3);
                    pah[2 * half]     = pack2(h0, h1b);
                    pah[2 * half + 1] = pack2(h2, h3);
                    pal[2 * half]     = pack2(
                        __float2bfloat16_rn(p0 - __bfloat162float(h0)),
                        __float2bfloat16_rn(p1 - __bfloat162float(h1b)));
                    pal[2 * half + 1] = pack2(
                        __float2bfloat16_rn(p2 - __bfloat162float(h2)),
                        __float2bfloat16_rn(p3 - __bfloat162float(h3)));
                }
                // reorder: mma a = {f2s.c01, f2s.c23, f2s+1.c01, f2s+1.c23}
                uint32_t ah2[4] = {pah[0], pah[1], pah[2], pah[3]};
                uint32_t al2[4] = {pal[0], pal[1], pal[2], pal[3]};
                #pragma unroll
                for (int j2 = 0; j2 < 4; j2++) {
                    uint32_t vh0, vh1, vh2, vh3, vl0, vl1, vl2, vl3;
                    uint32_t boff = (16 * s * FR + 8 * j2) * 4 + voff;
                    ldmx4t(vh0, vh1, vh2, vh3, vbase_h + boff);
                    ldmx4t(vl0, vl1, vl2, vl3, vbase_l + boff);
                    uint32_t bh0[2] = {vh0, vh1}, bh1[2] = {vh2, vh3};
                    uint32_t bl0[2] = {vl0, vl1}, bl1[2] = {vl2, vl3};
                    mma_bf16(of[2 * j2], ah2, bh0);
                    mma_bf16(of[2 * j2], al2, bh0);
                    mma_bf16(of[2 * j2], ah2, bl0);
                    mma_bf16(of[2 * j2 + 1], ah2, bh1);
                    mma_bf16(of[2 * j2 + 1], al2, bh1);
                    mma_bf16(of[2 * j2 + 1], ah2, bl1);
                }
            }
        }
        __syncthreads();
    }

    // ---- epilogue ----
    float i0 = 1.f / l0, i1 = 1.f / l1;
    float* ob0 = o + (size_t)(b * LSEQ + row0) * DM + h * DK;
    float* ob1 = o + (size_t)(b * LSEQ + row0 + 8) * DM + h * DK;
    #pragma unroll
    for (int n = 0; n < 8; n++) {
        int col = 8 * n + 2 * t4;
        *(float2*)(ob0 + col) = make_float2(of[n][0] * i0, of[n][1] * i0);
        *(float2*)(ob1 + col) = make_float2(of[n][2] * i1, of[n][3] * i1);
    }
}

// ===========================================================================
extern "C" void kernel_launch(void* const* d_in, const int* in_sizes, int n_in,
                              void* d_out, int out_size) {
    const float* x    = (const float*)d_in[0];
    const float* W_in = (const float*)d_in[1];
    const float* W_o  = (const float*)d_in[2];
    float* out = (float*)d_out;

    float *h, *qkv, *o;
    cudaGetSymbolAddress((void**)&h,   g_h);
    cudaGetSymbolAddress((void**)&qkv, g_qkv);
    cudaGetSymbolAddress((void**)&o,   g_o);

    cudaFuncSetAttribute(gemm_tc, cudaFuncAttributeMaxDynamicSharedMemorySize,
                         GEMM_SMEM);
    cudaFuncSetAttribute(flash_tc, cudaFuncAttributeMaxDynamicSharedMemorySize,
                         FLASH_SMEM);

    ln_kernel<<<TOKENS, 256>>>(x, h);

    dim3 g1(3 * DM / BN, TOKENS / BM);
    gemm_tc<<<g1, 256, GEMM_SMEM>>>(h, W_in, qkv, TOKENS, 3 * DM, DM);

    rope_kernel<<<TOKENS, 512>>>(qkv);

    dim3 g2(LSEQ / FQ, NH, NB);
    flash_tc<<<g2, 256, FLASH_SMEM>>>(qkv, o);

    dim3 g3(DM / BN, TOKENS / BM);
    gemm_tc<<<g3, 256, GEMM_SMEM>>>(o, W_o, out, TOKENS, DM, DM);
}